// round 10
// baseline (speedup 1.0000x reference)
#include <cuda_runtime.h>
#include <cuda_bf16.h>
#include <math.h>
#include <float.h>
#include <stdint.h>

// Problem constants
#define NTOT 65536          // B*H*W
#define CDIM 512            // channels / key dim
#define MDIM 512            // number of memory slots
#define HWDIM 4096          // H*W

// Output packing offsets (flat concat of the returned tuple, fp32)
#define OFF_UQ   0LL
#define OFF_UM   67108864LL           // 16*1024*4096
#define OFF_SQ   67371008LL           // + 512*512
#define OFF_SM   100925440LL          // + 65536*512
#define OFF_SEP  134479872LL          // + 65536*512
#define OFF_COMP 134479873LL

// ---------------- device scratch (no allocations allowed) ----------------
__device__ float          g_score[(size_t)NTOT * MDIM];  // score matrix
__device__ __nv_bfloat16  g_Ah[(size_t)NTOT * CDIM];     // qr hi split
__device__ __nv_bfloat16  g_Al[(size_t)NTOT * CDIM];     // qr lo split
__device__ __nv_bfloat16  g_Sh[(size_t)NTOT * CDIM];     // s_memory hi split
__device__ __nv_bfloat16  g_Sl[(size_t)NTOT * CDIM];     // s_memory lo split
__device__ __nv_bfloat16  g_Bh[(size_t)MDIM * CDIM];     // keys hi
__device__ __nv_bfloat16  g_Bl[(size_t)MDIM * CDIM];     // keys lo
__device__ __nv_bfloat16  g_BTh[(size_t)CDIM * MDIM];    // keysT hi
__device__ __nv_bfloat16  g_BTl[(size_t)CDIM * MDIM];    // keysT lo
__device__ float  g_cmax[MDIM];
__device__ float  g_csum[MDIM];                   // unshifted sum exp(score) per column
__device__ float  g_w[NTOT];
__device__ int    g_gi[NTOT];
__device__ int    g_count[MDIM];
__device__ int    g_offset[MDIM + 1];
__device__ int    g_cursor[MDIM];
__device__ int    g_list[NTOT];
__device__ double g_comp, g_sep;

// ---------------- helpers ----------------
__device__ __forceinline__ void atomicMaxF(float* addr, float val) {
    int* ia = (int*)addr;
    int old = *ia;
    while (__int_as_float(old) < val) {
        int assumed = old;
        old = atomicCAS(ia, assumed, __float_as_int(val));
        if (old == assumed) break;
    }
}
__device__ __forceinline__ void bf16split(float v, __nv_bfloat16& h, __nv_bfloat16& l) {
    h = __float2bfloat16(v);
    l = __float2bfloat16(v - __bfloat162float(h));
}

// ======================= bf16 3x-split warp-MMA GEMM =======================
// C[i, col0+j] = sum_k A[i,k] * B[col0+j, k]  with pre-split bf16 operands.
// CTA tile 128x128, K-chunk 32, double-buffered smem (2 x 32KB), cp.async.
// Stage layout (bytes): Ah 0..8K | Al 8K..16K | Bh 16K..24K | Bl 24K..32K
// Row = 64B (32 bf16), 4x16B chunks, chunk XOR-swizzled by (row>>1)&3.
// MMA issue order: three 16-MMA passes (ah*bh, al*bh, ah*bl) so same-accumulator
// RAW reuse distance is 16 issues (>= HMMA latency) instead of 2.

__device__ __forceinline__ void ldm4(uint32_t* r, uint32_t a) {
    asm volatile("ldmatrix.sync.aligned.m8n8.x4.shared.b16 {%0,%1,%2,%3}, [%4];"
        : "=r"(r[0]), "=r"(r[1]), "=r"(r[2]), "=r"(r[3]) : "r"(a));
}
__device__ __forceinline__ void mma16816(float* d, const uint32_t* a, uint32_t b0, uint32_t b1) {
    asm volatile("mma.sync.aligned.m16n8k16.row.col.f32.bf16.bf16.f32 "
        "{%0,%1,%2,%3}, {%4,%5,%6,%7}, {%8,%9}, {%0,%1,%2,%3};"
        : "+f"(d[0]), "+f"(d[1]), "+f"(d[2]), "+f"(d[3])
        : "r"(a[0]), "r"(a[1]), "r"(a[2]), "r"(a[3]), "r"(b0), "r"(b1));
}
__device__ __forceinline__ void cpa16(uint32_t dst, const void* src) {
    asm volatile("cp.async.cg.shared.global [%0], [%1], 16;" :: "r"(dst), "l"(src));
}

// Hoisted-address stage issue: each thread does 8 x 16B cp.async.
__device__ __forceinline__ void stage_issue(const __nv_bfloat16* pAh, const __nv_bfloat16* pAl,
                                            const __nv_bfloat16* pBh, const __nv_bfloat16* pBl,
                                            uint32_t stb, uint32_t d0, int koff) {
    cpa16(stb + d0,                 pAh + koff);
    cpa16(stb + d0 + 4096u,         pAh + koff + 32768);
    cpa16(stb + 8192u + d0,         pAl + koff);
    cpa16(stb + 8192u + d0 + 4096u, pAl + koff + 32768);
    cpa16(stb + 16384u + d0,        pBh + koff);
    cpa16(stb + 16384u + d0 + 4096u, pBh + koff + 32768);
    cpa16(stb + 24576u + d0,        pBl + koff);
    cpa16(stb + 24576u + d0 + 4096u, pBl + koff + 32768);
}

// EPI=0: write C row-major (N x 512) AND accumulate column softmax stats.
// EPI=1: write transposed into output: Cout[b*1024*4096 + (512+col0+d)*4096 + hw]
template <int EPI>
__global__ void __launch_bounds__(256, 2) k_mma(const __nv_bfloat16* __restrict__ Ah,
                                                const __nv_bfloat16* __restrict__ Al,
                                                const __nv_bfloat16* __restrict__ Bh,
                                                const __nv_bfloat16* __restrict__ Bl,
                                                float* __restrict__ Cout) {
    extern __shared__ char sm[];
    const int tid = threadIdx.x, lane = tid & 31, wid = tid >> 5;
    const size_t row0 = (size_t)blockIdx.y * 128;
    const int col0 = blockIdx.x * 128;
    const int warp_i = (wid & 3) * 32;      // 4 warps along i
    const int warp_j = (wid >> 2) * 64;     // 2 warps along j

    float acc[2][8][4];
    #pragma unroll
    for (int a = 0; a < 2; a++)
        #pragma unroll
        for (int b = 0; b < 8; b++)
            #pragma unroll
            for (int c = 0; c < 4; c++) acc[a][b][c] = 0.0f;

    const int lrow = (lane & 7) + ((lane >> 3) & 1) * 8;
    const int lsel = lane >> 4;
    const int arow = warp_i + lrow;
    const int asw  = (arow >> 1) & 3;
    const int brow = warp_j + lrow;
    const int bsw  = (brow >> 1) & 3;
    const uint32_t smb = (uint32_t)__cvta_generic_to_shared(sm);

    // hoisted cp.async addressing: this thread covers rows r0 and r0+64, chunk col cc4
    const int r0 = tid >> 2, cc4 = tid & 3;
    const uint32_t d0 = (uint32_t)(r0 * 64 + ((cc4 ^ ((r0 >> 1) & 3)) << 4));
    const __nv_bfloat16* pAh = Ah + (row0 + r0) * 512 + cc4 * 8;
    const __nv_bfloat16* pAl = Al + (row0 + r0) * 512 + cc4 * 8;
    const __nv_bfloat16* pBh = Bh + (size_t)(col0 + r0) * 512 + cc4 * 8;
    const __nv_bfloat16* pBl = Bl + (size_t)(col0 + r0) * 512 + cc4 * 8;

    stage_issue(pAh, pAl, pBh, pBl, smb, d0, 0);
    asm volatile("cp.async.commit_group;");

    #pragma unroll 2
    for (int ch = 0; ch < 16; ch++) {
        uint32_t stb = smb + (uint32_t)((ch & 1) << 15);
        if (ch < 15) {
            stage_issue(pAh, pAl, pBh, pBl, stb ^ 32768u, d0, (ch + 1) * 32);
            asm volatile("cp.async.commit_group;");
            asm volatile("cp.async.wait_group 1;");
        } else {
            asm volatile("cp.async.wait_group 0;");
        }
        __syncthreads();
        #pragma unroll
        for (int ks = 0; ks < 2; ks++) {
            int cidx = ks * 2 + lsel;
            uint32_t ah[2][4], al[2][4], bh[4][4], bl[4][4];
            #pragma unroll
            for (int fi = 0; fi < 2; fi++) {
                uint32_t ad = stb + (uint32_t)((arow + fi * 16) * 64 + ((cidx ^ asw) << 4));
                ldm4(ah[fi], ad);
                ldm4(al[fi], ad + 8192u);
            }
            #pragma unroll
            for (int g = 0; g < 4; g++) {
                uint32_t bd = stb + 16384u + (uint32_t)((brow + g * 16) * 64 + ((cidx ^ bsw) << 4));
                ldm4(bh[g], bd);
            }
            // pass 1: ah x bh -> 16 distinct accumulators (no RAW inside pass)
            #pragma unroll
            for (int fi = 0; fi < 2; fi++)
                #pragma unroll
                for (int g = 0; g < 4; g++) {
                    mma16816(acc[fi][2*g],   ah[fi], bh[g][0], bh[g][2]);
                    mma16816(acc[fi][2*g+1], ah[fi], bh[g][1], bh[g][3]);
                }
            // load bl now; its latency hides under pass 2
            #pragma unroll
            for (int g = 0; g < 4; g++) {
                uint32_t bd = stb + 24576u + (uint32_t)((brow + g * 16) * 64 + ((cidx ^ bsw) << 4));
                ldm4(bl[g], bd);
            }
            // pass 2: al x bh -> same 16 accs, reuse distance = 16 issues
            #pragma unroll
            for (int fi = 0; fi < 2; fi++)
                #pragma unroll
                for (int g = 0; g < 4; g++) {
                    mma16816(acc[fi][2*g],   al[fi], bh[g][0], bh[g][2]);
                    mma16816(acc[fi][2*g+1], al[fi], bh[g][1], bh[g][3]);
                }
            // pass 3: ah x bl -> same 16 accs, reuse distance = 16 issues
            #pragma unroll
            for (int fi = 0; fi < 2; fi++)
                #pragma unroll
                for (int g = 0; g < 4; g++) {
                    mma16816(acc[fi][2*g],   ah[fi], bl[g][0], bl[g][2]);
                    mma16816(acc[fi][2*g+1], ah[fi], bl[g][1], bl[g][3]);
                }
        }
        __syncthreads();
    }

    if (EPI == 0) {
        // plain row-major write
        #pragma unroll
        for (int fi = 0; fi < 2; fi++) {
            size_t r = row0 + warp_i + fi * 16 + (lane >> 2);
            #pragma unroll
            for (int fj = 0; fj < 8; fj++) {
                int cw = col0 + warp_j + fj * 8 + (lane & 3) * 2;
                *(float2*)&Cout[r * 512 + cw]       = make_float2(acc[fi][fj][0], acc[fi][fj][1]);
                *(float2*)&Cout[(r + 8) * 512 + cw] = make_float2(acc[fi][fj][2], acc[fi][fj][3]);
            }
        }
        // fused column stats: partial max + sum(exp) over this CTA's 128 rows
        float* smax = (float*)sm;          // [128]
        float* ssum = smax + 128;          // [128]
        float lmax[8][2], lsum[8][2];
        #pragma unroll
        for (int fj = 0; fj < 8; fj++)
            #pragma unroll
            for (int p = 0; p < 2; p++) {
                float a0 = acc[0][fj][p],     a1 = acc[0][fj][2 + p];
                float a2 = acc[1][fj][p],     a3 = acc[1][fj][2 + p];
                lmax[fj][p] = fmaxf(fmaxf(a0, a1), fmaxf(a2, a3));
                lsum[fj][p] = __expf(a0) + __expf(a1) + __expf(a2) + __expf(a3);
            }
        #pragma unroll
        for (int off = 4; off < 32; off <<= 1)
            #pragma unroll
            for (int fj = 0; fj < 8; fj++)
                #pragma unroll
                for (int p = 0; p < 2; p++) {
                    lmax[fj][p] = fmaxf(lmax[fj][p], __shfl_xor_sync(0xffffffffu, lmax[fj][p], off));
                    lsum[fj][p] += __shfl_xor_sync(0xffffffffu, lsum[fj][p], off);
                }
        #pragma unroll
        for (int kk = 0; kk < 4; kk++) {
            if ((wid & 3) == kk && lane < 4) {
                #pragma unroll
                for (int fj = 0; fj < 8; fj++)
                    #pragma unroll
                    for (int p = 0; p < 2; p++) {
                        int c = warp_j + fj * 8 + lane * 2 + p;
                        if (kk == 0) { smax[c] = lmax[fj][p]; ssum[c] = lsum[fj][p]; }
                        else { smax[c] = fmaxf(smax[c], lmax[fj][p]); ssum[c] += lsum[fj][p]; }
                    }
            }
            __syncthreads();
        }
        if (tid < 128) {
            atomicMaxF(&g_cmax[col0 + tid], smax[tid]);
            atomicAdd(&g_csum[col0 + tid], ssum[tid]);
        }
    } else {
        // transposed write via smem tile (two 64-row halves), stride 129 (conflict-free)
        float* tile = (float*)sm;
        size_t b = row0 >> 12;
        int hwb = (int)(row0 & 4095);
        float* obase = Cout + b * (1024LL * 4096LL) + (size_t)(512 + col0) * 4096;
        #pragma unroll
        for (int h = 0; h < 2; h++) {
            if (((wid & 3) >> 1) == h) {
                int rbase = warp_i - h * 64;    // 0 or 32
                #pragma unroll
                for (int fi = 0; fi < 2; fi++) {
                    int rr = rbase + fi * 16 + (lane >> 2);
                    #pragma unroll
                    for (int fj = 0; fj < 8; fj++) {
                        int cw = warp_j + fj * 8 + (lane & 3) * 2;
                        tile[rr * 129 + cw]           = acc[fi][fj][0];
                        tile[rr * 129 + cw + 1]       = acc[fi][fj][1];
                        tile[(rr + 8) * 129 + cw]     = acc[fi][fj][2];
                        tile[(rr + 8) * 129 + cw + 1] = acc[fi][fj][3];
                    }
                }
            }
            __syncthreads();
            int hw0 = hwb + h * 64;
            #pragma unroll
            for (int it = 0; it < 16; it++) {
                int d = wid * 16 + it;
                float v0 = tile[lane * 129 + d];
                float v1 = tile[(lane + 32) * 129 + d];
                obase[(size_t)d * 4096 + hw0 + lane]      = v0;
                obase[(size_t)d * 4096 + hw0 + 32 + lane] = v1;
            }
            __syncthreads();
        }
    }
}

// ---------------- keys prep: splits of keys and keys^T ----------------
__global__ void k_prepkeys(const float* __restrict__ keys) {
    __shared__ float t[32][33];
    int c0 = blockIdx.x * 32;
    int r0 = blockIdx.y * 32;
    int tx = threadIdx.x, ty = threadIdx.y;
    for (int r = ty; r < 32; r += 8) {
        float v = keys[(size_t)(r0 + r) * 512 + c0 + tx];
        t[r][tx] = v;
        __nv_bfloat16 h, l; bf16split(v, h, l);
        g_Bh[(size_t)(r0 + r) * 512 + c0 + tx] = h;
        g_Bl[(size_t)(r0 + r) * 512 + c0 + tx] = l;
    }
    __syncthreads();
    for (int r = ty; r < 32; r += 8) {
        float v = t[tx][r];
        __nv_bfloat16 h, l; bf16split(v, h, l);
        g_BTh[(size_t)(c0 + r) * 512 + r0 + tx] = h;
        g_BTl[(size_t)(c0 + r) * 512 + r0 + tx] = l;
    }
}

// ---------------- init ----------------
__global__ void k_init() {
    int t = blockIdx.x * blockDim.x + threadIdx.x;
    if (t < MDIM) { g_cmax[t] = -FLT_MAX; g_csum[t] = 0.0f; g_count[t] = 0; }
    if (t == 0) { g_comp = 0.0; g_sep = 0.0; }
}

// ---------------- L2 normalize + transpose to (N,C) + bf16 split + direct UQ output ----------------
__global__ void __launch_bounds__(256) k_normalize(const float* __restrict__ query,
                                                   float* __restrict__ out) {
    __shared__ float s[CDIM * 17];
    __shared__ float psum[256];
    __shared__ float rn[16];
    int p0 = blockIdx.x * 16;
    int b = p0 >> 12;
    int hw0 = p0 & 4095;
    const float* qb = query + (size_t)b * CDIM * HWDIM + hw0;
    int tid = threadIdx.x;
    #pragma unroll
    for (int it = 0; it < 32; it++) {
        int i = it * 256 + tid;
        int c = i >> 4, j = i & 15;
        s[c * 17 + j] = qb[(size_t)c * HWDIM + j];
    }
    __syncthreads();
    {
        int j = tid & 15, g = tid >> 4;
        float acc = 0.0f;
        #pragma unroll
        for (int cc = 0; cc < 32; cc++) {
            float v = s[(g * 32 + cc) * 17 + j];
            acc += v * v;
        }
        psum[tid] = acc;
    }
    __syncthreads();
    if (tid < 16) {
        float tot = 0.0f;
        #pragma unroll
        for (int g = 0; g < 16; g++) tot += psum[g * 16 + tid];
        rn[tid] = 1.0f / fmaxf(sqrtf(tot), 1e-12f);
    }
    __syncthreads();
    // bf16 splits in (N,C)
    #pragma unroll
    for (int it = 0; it < 32; it++) {
        int i = it * 256 + tid;
        int c = i & 511, j = i >> 9;
        float v = s[c * 17 + j] * rn[j];
        size_t idx = (size_t)(p0 + j) * CDIM + c;
        __nv_bfloat16 h, l; bf16split(v, h, l);
        g_Ah[idx] = h;
        g_Al[idx] = l;
    }
    // direct transposed output: updated_query[:, 0:512] = qr in (B,C,HW)
    float* ob = out + (size_t)b * (1024LL * 4096LL) + hw0;
    #pragma unroll
    for (int it = 0; it < 32; it++) {
        int i = it * 256 + tid;
        int c = i >> 4, j = i & 15;
        ob[(size_t)c * 4096 + j] = s[c * 17 + j] * rn[j];
    }
}

// ---------------- per-row pass: softmaxes, top2, w, losses, counts + sm splits ----------------
__global__ void __launch_bounds__(256) k_row(float* __restrict__ out_sq,
                                             float* __restrict__ out_sm,
                                             const float* __restrict__ keys) {
    __shared__ float cms[512];
    __shared__ float cssi[512];
    __shared__ double wcomp[8], wsep[8];
    for (int i = threadIdx.x; i < 512; i += 256) {
        float cm = g_cmax[i];
        cms[i] = cm;
        cssi[i] = 1.0f / (g_csum[i] * expf(-cm));
    }
    __syncthreads();
    int warp = threadIdx.x >> 5, lane = threadIdx.x & 31;
    size_t n = (size_t)blockIdx.x * 8 + warp;
    const float* srow = g_score + n * 512;
    float sc[16];
    #pragma unroll
    for (int t = 0; t < 16; t++) sc[t] = srow[lane + t * 32];

    float v1 = -FLT_MAX, v2 = -FLT_MAX; int i1 = 0, i2 = 0;
    #pragma unroll
    for (int t = 0; t < 16; t++) {
        int c = lane + t * 32; float v = sc[t];
        if (v > v1) { v2 = v1; i2 = i1; v1 = v; i1 = c; }
        else if (v > v2) { v2 = v; i2 = c; }
    }
    #pragma unroll
    for (int off = 16; off; off >>= 1) {
        float ov1 = __shfl_down_sync(0xffffffffu, v1, off);
        int   oi1 = __shfl_down_sync(0xffffffffu, i1, off);
        float ov2 = __shfl_down_sync(0xffffffffu, v2, off);
        int   oi2 = __shfl_down_sync(0xffffffffu, i2, off);
        if (ov1 > v1) { v2 = v1; i2 = i1; v1 = ov1; i1 = oi1; if (ov2 > v2) { v2 = ov2; i2 = oi2; } }
        else if (ov1 > v2) { v2 = ov1; i2 = oi1; }
    }
    v1 = __shfl_sync(0xffffffffu, v1, 0);
    i1 = __shfl_sync(0xffffffffu, i1, 0);
    i2 = __shfl_sync(0xffffffffu, i2, 0);

    float ex[16]; float rs = 0.0f;
    #pragma unroll
    for (int t = 0; t < 16; t++) { ex[t] = expf(sc[t] - v1); rs += ex[t]; }
    #pragma unroll
    for (int o = 16; o; o >>= 1) rs += __shfl_xor_sync(0xffffffffu, rs, o);
    float inv_rs = 1.0f / rs;
    float* smrow = out_sm + n * 512;
    float* sqrow = out_sq + n * 512;
    #pragma unroll
    for (int t = 0; t < 16; t++) {
        int c = lane + t * 32;
        float sv = ex[t] * inv_rs;
        smrow[c] = sv;
        sqrow[c] = expf(sc[t] - cms[c]) * cssi[c];
        __nv_bfloat16 h, l; bf16split(sv, h, l);
        g_Sh[n * 512 + c] = h;
        g_Sl[n * 512 + c] = l;
    }
    if (lane == 0) {
        g_gi[n] = i1;
        g_w[n] = expf(v1 - cms[i1]);
        atomicAdd(&g_count[i1], 1);
    }

    const __nv_bfloat16* qh = g_Ah + n * 512;
    const __nv_bfloat16* ql = g_Al + n * 512;
    const float* pk = keys + (size_t)i1 * 512;
    const float* nk = keys + (size_t)i2 * 512;
    float comp = 0.0f, dp = 0.0f, dn = 0.0f;
    #pragma unroll
    for (int t = 0; t < 16; t++) {
        int c = lane + t * 32;
        float q = __bfloat162float(qh[c]) + __bfloat162float(ql[c]);
        float p = pk[c], gg = nk[c];
        float d0 = q - p; comp += d0 * d0;
        float d1 = d0 + 1e-6f; dp += d1 * d1;
        float d2 = (q - gg) + 1e-6f; dn += d2 * d2;
    }
    #pragma unroll
    for (int o = 16; o; o >>= 1) {
        comp += __shfl_xor_sync(0xffffffffu, comp, o);
        dp   += __shfl_xor_sync(0xffffffffu, dp, o);
        dn   += __shfl_xor_sync(0xffffffffu, dn, o);
    }
    if (lane == 0) {
        wcomp[warp] = (double)comp;
        wsep[warp] = (double)fmaxf(0.0f, sqrtf(dp) - sqrtf(dn) + 1.0f);
    }
    __syncthreads();
    if (threadIdx.x == 0) {
        double c = 0.0, s = 0.0;
        for (int wv = 0; wv < 8; wv++) { c += wcomp[wv]; s += wsep[wv]; }
        atomicAdd(&g_comp, c);
        atomicAdd(&g_sep, s);
    }
}

// ---------------- counting sort of rows by gi ----------------
__global__ void __launch_bounds__(512) k_scan() {
    __shared__ int s[512];
    int t = threadIdx.x;
    int v = g_count[t];
    s[t] = v;
    __syncthreads();
    for (int off = 1; off < 512; off <<= 1) {
        int add = (t >= off) ? s[t - off] : 0;
        __syncthreads();
        s[t] += add;
        __syncthreads();
    }
    g_offset[t + 1] = s[t];
    if (t == 0) g_offset[0] = 0;
    g_cursor[t] = s[t] - v;
}

__global__ void k_scatter() {
    for (int n = blockIdx.x * blockDim.x + threadIdx.x; n < NTOT; n += gridDim.x * blockDim.x) {
        int m = g_gi[n];
        int idx = atomicAdd(&g_cursor[m], 1);
        g_list[idx] = n;
    }
}

// ---------------- memory update: segment sum + l2norm ----------------
__global__ void __launch_bounds__(512) k_update(const float* __restrict__ keys,
                                                float* __restrict__ outUM) {
    int m = blockIdx.x;
    int t = threadIdx.x;
    __shared__ int sln[256];
    __shared__ float slw[256];
    __shared__ float red[16];
    __shared__ float rn_s;
    int beg = g_offset[m], end = g_offset[m + 1];
    float acc = 0.0f;
    for (int base = beg; base < end; base += 256) {
        int cnt = min(256, end - base);
        __syncthreads();
        if (t < cnt) { int n = g_list[base + t]; sln[t] = n; slw[t] = g_w[n]; }
        __syncthreads();
        for (int i = 0; i < cnt; i++) {
            size_t idx = (size_t)sln[i] * 512 + t;
            float q = __bfloat162float(g_Ah[idx]) + __bfloat162float(g_Al[idx]);
            acc += slw[i] * q;
        }
    }
    float um = acc + keys[(size_t)m * 512 + t];
    float ss = um * um;
    #pragma unroll
    for (int o = 16; o; o >>= 1) ss += __shfl_xor_sync(0xffffffffu, ss, o);
    if ((t & 31) == 0) red[t >> 5] = ss;
    __syncthreads();
    if (t == 0) {
        float x = 0.0f;
        for (int i = 0; i < 16; i++) x += red[i];
        rn_s = 1.0f / fmaxf(sqrtf(x), 1e-12f);
    }
    __syncthreads();
    outUM[(size_t)m * 512 + t] = um * rn_s;
}

// ---------------- losses ----------------
__global__ void k_finalize(float* __restrict__ out) {
    out[OFF_SEP] = (float)(g_sep / (double)NTOT);
    out[OFF_COMP] = (float)(g_comp / ((double)NTOT * (double)CDIM));
}

// ---------------- launch ----------------
extern "C" void kernel_launch(void* const* d_in, const int* in_sizes, int n_in,
                              void* d_out, int out_size) {
    const float* query = (const float*)d_in[0];
    const float* keys  = (const float*)d_in[1];
    float* out = (float*)d_out;

    float* p_score = nullptr;
    __nv_bfloat16 *p_Ah = nullptr, *p_Al = nullptr, *p_Sh = nullptr, *p_Sl = nullptr;
    __nv_bfloat16 *p_Bh = nullptr, *p_Bl = nullptr, *p_BTh = nullptr, *p_BTl = nullptr;
    cudaGetSymbolAddress((void**)&p_score, g_score);
    cudaGetSymbolAddress((void**)&p_Ah, g_Ah);
    cudaGetSymbolAddress((void**)&p_Al, g_Al);
    cudaGetSymbolAddress((void**)&p_Sh, g_Sh);
    cudaGetSymbolAddress((void**)&p_Sl, g_Sl);
    cudaGetSymbolAddress((void**)&p_Bh, g_Bh);
    cudaGetSymbolAddress((void**)&p_Bl, g_Bl);
    cudaGetSymbolAddress((void**)&p_BTh, g_BTh);
    cudaGetSymbolAddress((void**)&p_BTl, g_BTl);

    cudaFuncSetAttribute(k_mma<0>, cudaFuncAttributeMaxDynamicSharedMemorySize, 65536);
    cudaFuncSetAttribute(k_mma<1>, cudaFuncAttributeMaxDynamicSharedMemorySize, 65536);

    k_init<<<2, 256>>>();
    k_normalize<<<NTOT / 16, 256>>>(query, out);
    k_prepkeys<<<dim3(16, 16), dim3(32, 8)>>>(keys);
    k_mma<0><<<dim3(4, NTOT / 128), 256, 65536>>>(p_Ah, p_Al, p_Bh, p_Bl, p_score);
    k_row<<<NTOT / 8, 256>>>(out + OFF_SQ, out + OFF_SM, keys);
    k_scan<<<1, 512>>>();
    k_scatter<<<64, 256>>>();
    k_update<<<MDIM, 512>>>(keys, out + OFF_UM);
    k_mma<1><<<dim3(4, NTOT / 128), 256, 65536>>>(p_Sh, p_Sl, p_BTh, p_BTl, out);
    k_finalize<<<1, 1>>>(out);
}

// round 11
// speedup vs baseline: 1.0112x; 1.0112x over previous
#include <cuda_runtime.h>
#include <cuda_bf16.h>
#include <math.h>
#include <float.h>
#include <stdint.h>

// Problem constants
#define NTOT 65536          // B*H*W
#define CDIM 512            // channels / key dim
#define MDIM 512            // number of memory slots
#define HWDIM 4096          // H*W

// Output packing offsets (flat concat of the returned tuple, fp32)
#define OFF_UQ   0LL
#define OFF_UM   67108864LL           // 16*1024*4096
#define OFF_SQ   67371008LL           // + 512*512
#define OFF_SM   100925440LL          // + 65536*512
#define OFF_SEP  134479872LL          // + 65536*512
#define OFF_COMP 134479873LL

// ---------------- device scratch (no allocations allowed) ----------------
__device__ float          g_E[(size_t)NTOT * MDIM];      // E = exp(score)
__device__ __nv_bfloat16  g_Ah[(size_t)NTOT * CDIM];     // qr hi split
__device__ __nv_bfloat16  g_Al[(size_t)NTOT * CDIM];     // qr lo split
__device__ __nv_bfloat16  g_Sh[(size_t)NTOT * CDIM];     // s_memory hi split
__device__ __nv_bfloat16  g_Sl[(size_t)NTOT * CDIM];     // s_memory lo split
__device__ __nv_bfloat16  g_Bh[(size_t)MDIM * CDIM];     // keys hi
__device__ __nv_bfloat16  g_Bl[(size_t)MDIM * CDIM];     // keys lo
__device__ __nv_bfloat16  g_BTh[(size_t)CDIM * MDIM];    // keysT hi
__device__ __nv_bfloat16  g_BTl[(size_t)CDIM * MDIM];    // keysT lo
__device__ float  g_cmax[MDIM];                   // column max of E
__device__ float  g_csum[MDIM];                   // column sum of E
__device__ float  g_w[NTOT];
__device__ int    g_gi[NTOT];
__device__ int    g_count[MDIM];
__device__ int    g_offset[MDIM + 1];
__device__ int    g_cursor[MDIM];
__device__ int    g_list[NTOT];
__device__ double g_comp, g_sep;

// ---------------- helpers ----------------
__device__ __forceinline__ void atomicMaxF(float* addr, float val) {
    int* ia = (int*)addr;
    int old = *ia;
    while (__int_as_float(old) < val) {
        int assumed = old;
        old = atomicCAS(ia, assumed, __float_as_int(val));
        if (old == assumed) break;
    }
}
__device__ __forceinline__ void bf16split(float v, __nv_bfloat16& h, __nv_bfloat16& l) {
    h = __float2bfloat16(v);
    l = __float2bfloat16(v - __bfloat162float(h));
}

// ======================= bf16 3x-split warp-MMA GEMM =======================
// C[i, col0+j] = sum_k A[i,k] * B[col0+j, k]  with pre-split bf16 operands.
// CTA tile 128x128, K-chunk 32, double-buffered smem (2 x 32KB), cp.async.
// Stage layout (bytes): Ah 0..8K | Al 8K..16K | Bh 16K..24K | Bl 24K..32K
// Row = 64B (32 bf16), 4x16B chunks, chunk XOR-swizzled by (row>>1)&3.

__device__ __forceinline__ void ldm4(uint32_t* r, uint32_t a) {
    asm volatile("ldmatrix.sync.aligned.m8n8.x4.shared.b16 {%0,%1,%2,%3}, [%4];"
        : "=r"(r[0]), "=r"(r[1]), "=r"(r[2]), "=r"(r[3]) : "r"(a));
}
__device__ __forceinline__ void mma16816(float* d, const uint32_t* a, uint32_t b0, uint32_t b1) {
    asm volatile("mma.sync.aligned.m16n8k16.row.col.f32.bf16.bf16.f32 "
        "{%0,%1,%2,%3}, {%4,%5,%6,%7}, {%8,%9}, {%0,%1,%2,%3};"
        : "+f"(d[0]), "+f"(d[1]), "+f"(d[2]), "+f"(d[3])
        : "r"(a[0]), "r"(a[1]), "r"(a[2]), "r"(a[3]), "r"(b0), "r"(b1));
}
__device__ __forceinline__ void cpa16(uint32_t dst, const void* src) {
    asm volatile("cp.async.cg.shared.global [%0], [%1], 16;" :: "r"(dst), "l"(src));
}

__device__ __forceinline__ void stage_issue(const __nv_bfloat16* pAh, const __nv_bfloat16* pAl,
                                            const __nv_bfloat16* pBh, const __nv_bfloat16* pBl,
                                            uint32_t stb, uint32_t d0, int koff) {
    cpa16(stb + d0,                 pAh + koff);
    cpa16(stb + d0 + 4096u,         pAh + koff + 32768);
    cpa16(stb + 8192u + d0,         pAl + koff);
    cpa16(stb + 8192u + d0 + 4096u, pAl + koff + 32768);
    cpa16(stb + 16384u + d0,        pBh + koff);
    cpa16(stb + 16384u + d0 + 4096u, pBh + koff + 32768);
    cpa16(stb + 24576u + d0,        pBl + koff);
    cpa16(stb + 24576u + d0 + 4096u, pBl + koff + 32768);
}

// EPI=0: write E = exp(score) row-major (N x 512) AND accumulate col max/sum of E.
// EPI=1: write transposed into output: Cout[b*1024*4096 + (512+col0+d)*4096 + hw]
template <int EPI>
__global__ void __launch_bounds__(256, 2) k_mma(const __nv_bfloat16* __restrict__ Ah,
                                                const __nv_bfloat16* __restrict__ Al,
                                                const __nv_bfloat16* __restrict__ Bh,
                                                const __nv_bfloat16* __restrict__ Bl,
                                                float* __restrict__ Cout) {
    extern __shared__ char sm[];
    const int tid = threadIdx.x, lane = tid & 31, wid = tid >> 5;
    const size_t row0 = (size_t)blockIdx.y * 128;
    const int col0 = blockIdx.x * 128;
    const int warp_i = (wid & 3) * 32;      // 4 warps along i
    const int warp_j = (wid >> 2) * 64;     // 2 warps along j

    float acc[2][8][4];
    #pragma unroll
    for (int a = 0; a < 2; a++)
        #pragma unroll
        for (int b = 0; b < 8; b++)
            #pragma unroll
            for (int c = 0; c < 4; c++) acc[a][b][c] = 0.0f;

    const int lrow = (lane & 7) + ((lane >> 3) & 1) * 8;
    const int lsel = lane >> 4;
    const int arow = warp_i + lrow;
    const int asw  = (arow >> 1) & 3;
    const int brow = warp_j + lrow;
    const int bsw  = (brow >> 1) & 3;
    const uint32_t smb = (uint32_t)__cvta_generic_to_shared(sm);

    const int r0 = tid >> 2, cc4 = tid & 3;
    const uint32_t d0 = (uint32_t)(r0 * 64 + ((cc4 ^ ((r0 >> 1) & 3)) << 4));
    const __nv_bfloat16* pAh = Ah + (row0 + r0) * 512 + cc4 * 8;
    const __nv_bfloat16* pAl = Al + (row0 + r0) * 512 + cc4 * 8;
    const __nv_bfloat16* pBh = Bh + (size_t)(col0 + r0) * 512 + cc4 * 8;
    const __nv_bfloat16* pBl = Bl + (size_t)(col0 + r0) * 512 + cc4 * 8;

    stage_issue(pAh, pAl, pBh, pBl, smb, d0, 0);
    asm volatile("cp.async.commit_group;");

    #pragma unroll 2
    for (int ch = 0; ch < 16; ch++) {
        uint32_t stb = smb + (uint32_t)((ch & 1) << 15);
        if (ch < 15) {
            stage_issue(pAh, pAl, pBh, pBl, stb ^ 32768u, d0, (ch + 1) * 32);
            asm volatile("cp.async.commit_group;");
            asm volatile("cp.async.wait_group 1;");
        } else {
            asm volatile("cp.async.wait_group 0;");
        }
        __syncthreads();
        #pragma unroll
        for (int ks = 0; ks < 2; ks++) {
            int cidx = ks * 2 + lsel;
            uint32_t ah[2][4], al[2][4], bh[4][4], bl[4][4];
            #pragma unroll
            for (int fi = 0; fi < 2; fi++) {
                uint32_t ad = stb + (uint32_t)((arow + fi * 16) * 64 + ((cidx ^ asw) << 4));
                ldm4(ah[fi], ad);
                ldm4(al[fi], ad + 8192u);
            }
            #pragma unroll
            for (int g = 0; g < 4; g++) {
                uint32_t bd = stb + 16384u + (uint32_t)((brow + g * 16) * 64 + ((cidx ^ bsw) << 4));
                ldm4(bh[g], bd);
            }
            #pragma unroll
            for (int fi = 0; fi < 2; fi++)
                #pragma unroll
                for (int g = 0; g < 4; g++) {
                    mma16816(acc[fi][2*g],   ah[fi], bh[g][0], bh[g][2]);
                    mma16816(acc[fi][2*g+1], ah[fi], bh[g][1], bh[g][3]);
                }
            #pragma unroll
            for (int g = 0; g < 4; g++) {
                uint32_t bd = stb + 24576u + (uint32_t)((brow + g * 16) * 64 + ((cidx ^ bsw) << 4));
                ldm4(bl[g], bd);
            }
            #pragma unroll
            for (int fi = 0; fi < 2; fi++)
                #pragma unroll
                for (int g = 0; g < 4; g++) {
                    mma16816(acc[fi][2*g],   al[fi], bh[g][0], bh[g][2]);
                    mma16816(acc[fi][2*g+1], al[fi], bh[g][1], bh[g][3]);
                }
            #pragma unroll
            for (int fi = 0; fi < 2; fi++)
                #pragma unroll
                for (int g = 0; g < 4; g++) {
                    mma16816(acc[fi][2*g],   ah[fi], bl[g][0], bl[g][2]);
                    mma16816(acc[fi][2*g+1], ah[fi], bl[g][1], bl[g][3]);
                }
        }
        __syncthreads();
    }

    if (EPI == 0) {
        // E = exp(score): compute once, write E, derive col stats from E
        float e[2][8][4];
        #pragma unroll
        for (int fi = 0; fi < 2; fi++)
            #pragma unroll
            for (int fj = 0; fj < 8; fj++)
                #pragma unroll
                for (int p = 0; p < 4; p++)
                    e[fi][fj][p] = __expf(acc[fi][fj][p]);
        #pragma unroll
        for (int fi = 0; fi < 2; fi++) {
            size_t r = row0 + warp_i + fi * 16 + (lane >> 2);
            #pragma unroll
            for (int fj = 0; fj < 8; fj++) {
                int cw = col0 + warp_j + fj * 8 + (lane & 3) * 2;
                *(float2*)&Cout[r * 512 + cw]       = make_float2(e[fi][fj][0], e[fi][fj][1]);
                *(float2*)&Cout[(r + 8) * 512 + cw] = make_float2(e[fi][fj][2], e[fi][fj][3]);
            }
        }
        // fused column stats on E: partial max + sum over this CTA's 128 rows
        float* smax = (float*)sm;          // [128]
        float* ssum = smax + 128;          // [128]
        float lmax[8][2], lsum[8][2];
        #pragma unroll
        for (int fj = 0; fj < 8; fj++)
            #pragma unroll
            for (int p = 0; p < 2; p++) {
                float a0 = e[0][fj][p], a1 = e[0][fj][2 + p];
                float a2 = e[1][fj][p], a3 = e[1][fj][2 + p];
                lmax[fj][p] = fmaxf(fmaxf(a0, a1), fmaxf(a2, a3));
                lsum[fj][p] = a0 + a1 + a2 + a3;
            }
        #pragma unroll
        for (int off = 4; off < 32; off <<= 1)
            #pragma unroll
            for (int fj = 0; fj < 8; fj++)
                #pragma unroll
                for (int p = 0; p < 2; p++) {
                    lmax[fj][p] = fmaxf(lmax[fj][p], __shfl_xor_sync(0xffffffffu, lmax[fj][p], off));
                    lsum[fj][p] += __shfl_xor_sync(0xffffffffu, lsum[fj][p], off);
                }
        #pragma unroll
        for (int kk = 0; kk < 4; kk++) {
            if ((wid & 3) == kk && lane < 4) {
                #pragma unroll
                for (int fj = 0; fj < 8; fj++)
                    #pragma unroll
                    for (int p = 0; p < 2; p++) {
                        int c = warp_j + fj * 8 + lane * 2 + p;
                        if (kk == 0) { smax[c] = lmax[fj][p]; ssum[c] = lsum[fj][p]; }
                        else { smax[c] = fmaxf(smax[c], lmax[fj][p]); ssum[c] += lsum[fj][p]; }
                    }
            }
            __syncthreads();
        }
        if (tid < 128) {
            atomicMaxF(&g_cmax[col0 + tid], smax[tid]);
            atomicAdd(&g_csum[col0 + tid], ssum[tid]);
        }
    } else {
        // transposed write via smem tile (two 64-row halves), stride 129 (conflict-free)
        float* tile = (float*)sm;
        size_t b = row0 >> 12;
        int hwb = (int)(row0 & 4095);
        float* obase = Cout + b * (1024LL * 4096LL) + (size_t)(512 + col0) * 4096;
        #pragma unroll
        for (int h = 0; h < 2; h++) {
            if (((wid & 3) >> 1) == h) {
                int rbase = warp_i - h * 64;    // 0 or 32
                #pragma unroll
                for (int fi = 0; fi < 2; fi++) {
                    int rr = rbase + fi * 16 + (lane >> 2);
                    #pragma unroll
                    for (int fj = 0; fj < 8; fj++) {
                        int cw = warp_j + fj * 8 + (lane & 3) * 2;
                        tile[rr * 129 + cw]           = acc[fi][fj][0];
                        tile[rr * 129 + cw + 1]       = acc[fi][fj][1];
                        tile[(rr + 8) * 129 + cw]     = acc[fi][fj][2];
                        tile[(rr + 8) * 129 + cw + 1] = acc[fi][fj][3];
                    }
                }
            }
            __syncthreads();
            int hw0 = hwb + h * 64;
            #pragma unroll
            for (int it = 0; it < 16; it++) {
                int d = wid * 16 + it;
                float v0 = tile[lane * 129 + d];
                float v1 = tile[(lane + 32) * 129 + d];
                obase[(size_t)d * 4096 + hw0 + lane]      = v0;
                obase[(size_t)d * 4096 + hw0 + 32 + lane] = v1;
            }
            __syncthreads();
        }
    }
}

// ---------------- keys prep: splits of keys and keys^T ----------------
__global__ void k_prepkeys(const float* __restrict__ keys) {
    __shared__ float t[32][33];
    int c0 = blockIdx.x * 32;
    int r0 = blockIdx.y * 32;
    int tx = threadIdx.x, ty = threadIdx.y;
    for (int r = ty; r < 32; r += 8) {
        float v = keys[(size_t)(r0 + r) * 512 + c0 + tx];
        t[r][tx] = v;
        __nv_bfloat16 h, l; bf16split(v, h, l);
        g_Bh[(size_t)(r0 + r) * 512 + c0 + tx] = h;
        g_Bl[(size_t)(r0 + r) * 512 + c0 + tx] = l;
    }
    __syncthreads();
    for (int r = ty; r < 32; r += 8) {
        float v = t[tx][r];
        __nv_bfloat16 h, l; bf16split(v, h, l);
        g_BTh[(size_t)(c0 + r) * 512 + r0 + tx] = h;
        g_BTl[(size_t)(c0 + r) * 512 + r0 + tx] = l;
    }
}

// ---------------- init ----------------
__global__ void k_init() {
    int t = blockIdx.x * blockDim.x + threadIdx.x;
    if (t < MDIM) { g_cmax[t] = 0.0f; g_csum[t] = 0.0f; g_count[t] = 0; }
    if (t == 0) { g_comp = 0.0; g_sep = 0.0; }
}

// ---------------- L2 normalize + transpose to (N,C) + bf16 split + direct UQ output ----------------
__global__ void __launch_bounds__(256) k_normalize(const float* __restrict__ query,
                                                   float* __restrict__ out) {
    __shared__ float s[CDIM * 17];
    __shared__ float psum[256];
    __shared__ float rn[16];
    int p0 = blockIdx.x * 16;
    int b = p0 >> 12;
    int hw0 = p0 & 4095;
    const float* qb = query + (size_t)b * CDIM * HWDIM + hw0;
    int tid = threadIdx.x;
    #pragma unroll
    for (int it = 0; it < 32; it++) {
        int i = it * 256 + tid;
        int c = i >> 4, j = i & 15;
        s[c * 17 + j] = qb[(size_t)c * HWDIM + j];
    }
    __syncthreads();
    {
        int j = tid & 15, g = tid >> 4;
        float acc = 0.0f;
        #pragma unroll
        for (int cc = 0; cc < 32; cc++) {
            float v = s[(g * 32 + cc) * 17 + j];
            acc += v * v;
        }
        psum[tid] = acc;
    }
    __syncthreads();
    if (tid < 16) {
        float tot = 0.0f;
        #pragma unroll
        for (int g = 0; g < 16; g++) tot += psum[g * 16 + tid];
        rn[tid] = 1.0f / fmaxf(sqrtf(tot), 1e-12f);
    }
    __syncthreads();
    #pragma unroll
    for (int it = 0; it < 32; it++) {
        int i = it * 256 + tid;
        int c = i & 511, j = i >> 9;
        float v = s[c * 17 + j] * rn[j];
        size_t idx = (size_t)(p0 + j) * CDIM + c;
        __nv_bfloat16 h, l; bf16split(v, h, l);
        g_Ah[idx] = h;
        g_Al[idx] = l;
    }
    float* ob = out + (size_t)b * (1024LL * 4096LL) + hw0;
    #pragma unroll
    for (int it = 0; it < 32; it++) {
        int i = it * 256 + tid;
        int c = i >> 4, j = i & 15;
        ob[(size_t)c * 4096 + j] = s[c * 17 + j] * rn[j];
    }
}

// ---------------- per-row pass on E: softmaxes, top2, w, losses, counts + sm splits ----------------
__global__ void __launch_bounds__(256) k_row(float* __restrict__ out_sq,
                                             float* __restrict__ out_sm,
                                             const float* __restrict__ keys) {
    __shared__ float cinv[512];
    __shared__ double wcomp[8], wsep[8];
    for (int i = threadIdx.x; i < 512; i += 256)
        cinv[i] = 1.0f / g_csum[i];
    __syncthreads();
    int warp = threadIdx.x >> 5, lane = threadIdx.x & 31;
    size_t n = (size_t)blockIdx.x * 8 + warp;
    const float* erow = g_E + n * 512;
    float ev[16];
    #pragma unroll
    for (int t = 0; t < 16; t++) ev[t] = erow[lane + t * 32];

    // top2 on E (exp is monotone -> same indices as on score)
    float v1 = -FLT_MAX, v2 = -FLT_MAX; int i1 = 0, i2 = 0;
    #pragma unroll
    for (int t = 0; t < 16; t++) {
        int c = lane + t * 32; float v = ev[t];
        if (v > v1) { v2 = v1; i2 = i1; v1 = v; i1 = c; }
        else if (v > v2) { v2 = v; i2 = c; }
    }
    #pragma unroll
    for (int off = 16; off; off >>= 1) {
        float ov1 = __shfl_down_sync(0xffffffffu, v1, off);
        int   oi1 = __shfl_down_sync(0xffffffffu, i1, off);
        float ov2 = __shfl_down_sync(0xffffffffu, v2, off);
        int   oi2 = __shfl_down_sync(0xffffffffu, i2, off);
        if (ov1 > v1) { v2 = v1; i2 = i1; v1 = ov1; i1 = oi1; if (ov2 > v2) { v2 = ov2; i2 = oi2; } }
        else if (ov1 > v2) { v2 = ov1; i2 = oi1; }
    }
    v1 = __shfl_sync(0xffffffffu, v1, 0);
    i1 = __shfl_sync(0xffffffffu, i1, 0);
    i2 = __shfl_sync(0xffffffffu, i2, 0);

    // row sum of E
    float rs = 0.0f;
    #pragma unroll
    for (int t = 0; t < 16; t++) rs += ev[t];
    #pragma unroll
    for (int o = 16; o; o >>= 1) rs += __shfl_xor_sync(0xffffffffu, rs, o);
    float inv_rs = 1.0f / rs;
    float* smrow = out_sm + n * 512;
    float* sqrow = out_sq + n * 512;
    #pragma unroll
    for (int t = 0; t < 16; t++) {
        int c = lane + t * 32;
        float sv = ev[t] * inv_rs;
        smrow[c] = sv;
        sqrow[c] = ev[t] * cinv[c];
        __nv_bfloat16 h, l; bf16split(sv, h, l);
        g_Sh[n * 512 + c] = h;
        g_Sl[n * 512 + c] = l;
    }
    if (lane == 0) {
        g_gi[n] = i1;
        g_w[n] = v1 / g_cmax[i1];      // = s_query[n,i1] / colmax(s_query)[i1]
        atomicAdd(&g_count[i1], 1);
    }

    const __nv_bfloat16* qh = g_Ah + n * 512;
    const __nv_bfloat16* ql = g_Al + n * 512;
    const float* pk = keys + (size_t)i1 * 512;
    const float* nk = keys + (size_t)i2 * 512;
    float comp = 0.0f, dp = 0.0f, dn = 0.0f;
    #pragma unroll
    for (int t = 0; t < 16; t++) {
        int c = lane + t * 32;
        float q = __bfloat162float(qh[c]) + __bfloat162float(ql[c]);
        float p = pk[c], gg = nk[c];
        float d0 = q - p; comp += d0 * d0;
        float d1 = d0 + 1e-6f; dp += d1 * d1;
        float d2 = (q - gg) + 1e-6f; dn += d2 * d2;
    }
    #pragma unroll
    for (int o = 16; o; o >>= 1) {
        comp += __shfl_xor_sync(0xffffffffu, comp, o);
        dp   += __shfl_xor_sync(0xffffffffu, dp, o);
        dn   += __shfl_xor_sync(0xffffffffu, dn, o);
    }
    if (lane == 0) {
        wcomp[warp] = (double)comp;
        wsep[warp] = (double)fmaxf(0.0f, sqrtf(dp) - sqrtf(dn) + 1.0f);
    }
    __syncthreads();
    if (threadIdx.x == 0) {
        double c = 0.0, s = 0.0;
        for (int wv = 0; wv < 8; wv++) { c += wcomp[wv]; s += wsep[wv]; }
        atomicAdd(&g_comp, c);
        atomicAdd(&g_sep, s);
    }
}

// ---------------- counting sort of rows by gi ----------------
__global__ void __launch_bounds__(512) k_scan() {
    __shared__ int s[512];
    int t = threadIdx.x;
    int v = g_count[t];
    s[t] = v;
    __syncthreads();
    for (int off = 1; off < 512; off <<= 1) {
        int add = (t >= off) ? s[t - off] : 0;
        __syncthreads();
        s[t] += add;
        __syncthreads();
    }
    g_offset[t + 1] = s[t];
    if (t == 0) g_offset[0] = 0;
    g_cursor[t] = s[t] - v;
}

__global__ void k_scatter() {
    for (int n = blockIdx.x * blockDim.x + threadIdx.x; n < NTOT; n += gridDim.x * blockDim.x) {
        int m = g_gi[n];
        int idx = atomicAdd(&g_cursor[m], 1);
        g_list[idx] = n;
    }
}

// ---------------- memory update: segment sum + l2norm ----------------
__global__ void __launch_bounds__(512) k_update(const float* __restrict__ keys,
                                                float* __restrict__ outUM) {
    int m = blockIdx.x;
    int t = threadIdx.x;
    __shared__ int sln[256];
    __shared__ float slw[256];
    __shared__ float red[16];
    __shared__ float rn_s;
    int beg = g_offset[m], end = g_offset[m + 1];
    float acc = 0.0f;
    for (int base = beg; base < end; base += 256) {
        int cnt = min(256, end - base);
        __syncthreads();
        if (t < cnt) { int n = g_list[base + t]; sln[t] = n; slw[t] = g_w[n]; }
        __syncthreads();
        for (int i = 0; i < cnt; i++) {
            size_t idx = (size_t)sln[i] * 512 + t;
            float q = __bfloat162float(g_Ah[idx]) + __bfloat162float(g_Al[idx]);
            acc += slw[i] * q;
        }
    }
    float um = acc + keys[(size_t)m * 512 + t];
    float ss = um * um;
    #pragma unroll
    for (int o = 16; o; o >>= 1) ss += __shfl_xor_sync(0xffffffffu, ss, o);
    if ((t & 31) == 0) red[t >> 5] = ss;
    __syncthreads();
    if (t == 0) {
        float x = 0.0f;
        for (int i = 0; i < 16; i++) x += red[i];
        rn_s = 1.0f / fmaxf(sqrtf(x), 1e-12f);
    }
    __syncthreads();
    outUM[(size_t)m * 512 + t] = um * rn_s;
}

// ---------------- losses ----------------
__global__ void k_finalize(float* __restrict__ out) {
    out[OFF_SEP] = (float)(g_sep / (double)NTOT);
    out[OFF_COMP] = (float)(g_comp / ((double)NTOT * (double)CDIM));
}

// ---------------- launch ----------------
extern "C" void kernel_launch(void* const* d_in, const int* in_sizes, int n_in,
                              void* d_out, int out_size) {
    const float* query = (const float*)d_in[0];
    const float* keys  = (const float*)d_in[1];
    float* out = (float*)d_out;

    float* p_E = nullptr;
    __nv_bfloat16 *p_Ah = nullptr, *p_Al = nullptr, *p_Sh = nullptr, *p_Sl = nullptr;
    __nv_bfloat16 *p_Bh = nullptr, *p_Bl = nullptr, *p_BTh = nullptr, *p_BTl = nullptr;
    cudaGetSymbolAddress((void**)&p_E, g_E);
    cudaGetSymbolAddress((void**)&p_Ah, g_Ah);
    cudaGetSymbolAddress((void**)&p_Al, g_Al);
    cudaGetSymbolAddress((void**)&p_Sh, g_Sh);
    cudaGetSymbolAddress((void**)&p_Sl, g_Sl);
    cudaGetSymbolAddress((void**)&p_Bh, g_Bh);
    cudaGetSymbolAddress((void**)&p_Bl, g_Bl);
    cudaGetSymbolAddress((void**)&p_BTh, g_BTh);
    cudaGetSymbolAddress((void**)&p_BTl, g_BTl);

    cudaFuncSetAttribute(k_mma<0>, cudaFuncAttributeMaxDynamicSharedMemorySize, 65536);
    cudaFuncSetAttribute(k_mma<1>, cudaFuncAttributeMaxDynamicSharedMemorySize, 65536);

    k_init<<<2, 256>>>();
    k_normalize<<<NTOT / 16, 256>>>(query, out);
    k_prepkeys<<<dim3(16, 16), dim3(32, 8)>>>(keys);
    k_mma<0><<<dim3(4, NTOT / 128), 256, 65536>>>(p_Ah, p_Al, p_Bh, p_Bl, p_E);
    k_row<<<NTOT / 8, 256>>>(out + OFF_SQ, out + OFF_SM, keys);
    k_scan<<<1, 512>>>();
    k_scatter<<<64, 256>>>();
    k_update<<<MDIM, 512>>>(keys, out + OFF_UM);
    k_mma<1><<<dim3(4, NTOT / 128), 256, 65536>>>(p_Sh, p_Sl, p_BTh, p_BTl, out);
    k_finalize<<<1, 1>>>(out);
}

// round 12
// speedup vs baseline: 1.0245x; 1.0132x over previous
#include <cuda_runtime.h>
#include <cuda_bf16.h>
#include <math.h>
#include <float.h>
#include <stdint.h>

// Problem constants
#define NTOT 65536          // B*H*W
#define CDIM 512            // channels / key dim
#define MDIM 512            // number of memory slots
#define HWDIM 4096          // H*W

// Output packing offsets (flat concat of the returned tuple, fp32)
#define OFF_UQ   0LL
#define OFF_UM   67108864LL           // 16*1024*4096
#define OFF_SQ   67371008LL           // + 512*512
#define OFF_SM   100925440LL          // + 65536*512
#define OFF_SEP  134479872LL          // + 65536*512
#define OFF_COMP 134479873LL

// ---------------- device scratch (no allocations allowed) ----------------
__device__ float          g_E[(size_t)NTOT * MDIM];      // E = exp(score)
__device__ __nv_bfloat16  g_Ah[(size_t)NTOT * CDIM];     // qr hi split
__device__ __nv_bfloat16  g_Al[(size_t)NTOT * CDIM];     // qr lo split
__device__ __nv_bfloat16  g_Sh[(size_t)NTOT * CDIM];     // s_memory hi split
__device__ __nv_bfloat16  g_Sl[(size_t)NTOT * CDIM];     // s_memory lo split
__device__ __nv_bfloat16  g_Bh[(size_t)MDIM * CDIM];     // keys hi
__device__ __nv_bfloat16  g_Bl[(size_t)MDIM * CDIM];     // keys lo
__device__ __nv_bfloat16  g_BTh[(size_t)CDIM * MDIM];    // keysT hi
__device__ __nv_bfloat16  g_BTl[(size_t)CDIM * MDIM];    // keysT lo
__device__ float  g_cmax[MDIM];                   // column max of E
__device__ float  g_csum[MDIM];                   // column sum of E
__device__ float  g_w[NTOT];
__device__ int    g_gi[NTOT];
__device__ int    g_count[MDIM];
__device__ int    g_offset[MDIM + 1];
__device__ int    g_cursor[MDIM];
__device__ int    g_list[NTOT];
__device__ double g_comp, g_sep;

// ---------------- helpers ----------------
__device__ __forceinline__ void atomicMaxF(float* addr, float val) {
    int* ia = (int*)addr;
    int old = *ia;
    while (__int_as_float(old) < val) {
        int assumed = old;
        old = atomicCAS(ia, assumed, __float_as_int(val));
        if (old == assumed) break;
    }
}
__device__ __forceinline__ void bf16split(float v, __nv_bfloat16& h, __nv_bfloat16& l) {
    h = __float2bfloat16(v);
    l = __float2bfloat16(v - __bfloat162float(h));
}

// ======================= bf16 3x-split warp-MMA GEMM =======================
// C[i, col0+j] = sum_k A[i,k] * B[col0+j, k]  with pre-split bf16 operands.
// CTA tile 64x128 (8 warps, warp tile 32x32), K-chunk 32, double-buffered
// smem (2 x 24KB), cp.async. 3 CTAs/SM for latency hiding.
// Stage layout (bytes): Ah 0..4K | Al 4K..8K | Bh 8K..16K | Bl 16K..24K
// Row = 64B (32 bf16), 4x16B chunks, chunk XOR-swizzled by (row>>1)&3.

__device__ __forceinline__ void ldm4(uint32_t* r, uint32_t a) {
    asm volatile("ldmatrix.sync.aligned.m8n8.x4.shared.b16 {%0,%1,%2,%3}, [%4];"
        : "=r"(r[0]), "=r"(r[1]), "=r"(r[2]), "=r"(r[3]) : "r"(a));
}
__device__ __forceinline__ void mma16816(float* d, const uint32_t* a, uint32_t b0, uint32_t b1) {
    asm volatile("mma.sync.aligned.m16n8k16.row.col.f32.bf16.bf16.f32 "
        "{%0,%1,%2,%3}, {%4,%5,%6,%7}, {%8,%9}, {%0,%1,%2,%3};"
        : "+f"(d[0]), "+f"(d[1]), "+f"(d[2]), "+f"(d[3])
        : "r"(a[0]), "r"(a[1]), "r"(a[2]), "r"(a[3]), "r"(b0), "r"(b1));
}
__device__ __forceinline__ void cpa16(uint32_t dst, const void* src) {
    asm volatile("cp.async.cg.shared.global [%0], [%1], 16;" :: "r"(dst), "l"(src));
}

// Stage = 24KB: each thread issues 6 x 16B cp.async.
// Thread covers A row r0 (one 16B) and B rows r0, r0+64 per region.
__device__ __forceinline__ void stage_issue(const __nv_bfloat16* pAh, const __nv_bfloat16* pAl,
                                            const __nv_bfloat16* pBh, const __nv_bfloat16* pBl,
                                            uint32_t stb, uint32_t d0, int koff) {
    cpa16(stb + d0,                  pAh + koff);
    cpa16(stb + 4096u + d0,          pAl + koff);
    cpa16(stb + 8192u + d0,          pBh + koff);
    cpa16(stb + 8192u + d0 + 4096u,  pBh + koff + 32768);
    cpa16(stb + 16384u + d0,         pBl + koff);
    cpa16(stb + 16384u + d0 + 4096u, pBl + koff + 32768);
}

// EPI=0: write E = exp(score) row-major (N x 512) AND accumulate col max/sum of E.
// EPI=1: write transposed into output: Cout[b*1024*4096 + (512+col0+d)*4096 + hw]
template <int EPI>
__global__ void __launch_bounds__(256, 3) k_mma(const __nv_bfloat16* __restrict__ Ah,
                                                const __nv_bfloat16* __restrict__ Al,
                                                const __nv_bfloat16* __restrict__ Bh,
                                                const __nv_bfloat16* __restrict__ Bl,
                                                float* __restrict__ Cout) {
    extern __shared__ char sm[];
    const int tid = threadIdx.x, lane = tid & 31, wid = tid >> 5;
    const size_t row0 = (size_t)blockIdx.y * 64;
    const int col0 = blockIdx.x * 128;
    const int warp_i = (wid & 1) * 32;      // 2 warps along i
    const int warp_j = (wid >> 1) * 32;     // 4 warps along j

    float acc[2][4][4];
    #pragma unroll
    for (int a = 0; a < 2; a++)
        #pragma unroll
        for (int b = 0; b < 4; b++)
            #pragma unroll
            for (int c = 0; c < 4; c++) acc[a][b][c] = 0.0f;

    const int lrow = (lane & 7) + ((lane >> 3) & 1) * 8;
    const int lsel = lane >> 4;
    const int arow = warp_i + lrow;
    const int asw  = (arow >> 1) & 3;
    const int brow = warp_j + lrow;
    const int bsw  = (brow >> 1) & 3;
    const uint32_t smb = (uint32_t)__cvta_generic_to_shared(sm);

    // hoisted cp.async addressing: thread covers A row r0, B rows r0 & r0+64, chunk col cc4
    const int r0 = tid >> 2, cc4 = tid & 3;
    const uint32_t d0 = (uint32_t)(r0 * 64 + ((cc4 ^ ((r0 >> 1) & 3)) << 4));
    const __nv_bfloat16* pAh = Ah + (row0 + r0) * 512 + cc4 * 8;
    const __nv_bfloat16* pAl = Al + (row0 + r0) * 512 + cc4 * 8;
    const __nv_bfloat16* pBh = Bh + (size_t)(col0 + r0) * 512 + cc4 * 8;
    const __nv_bfloat16* pBl = Bl + (size_t)(col0 + r0) * 512 + cc4 * 8;

    stage_issue(pAh, pAl, pBh, pBl, smb, d0, 0);
    asm volatile("cp.async.commit_group;");

    #pragma unroll 2
    for (int ch = 0; ch < 16; ch++) {
        uint32_t stb = smb + (uint32_t)((ch & 1) ? 24576 : 0);
        if (ch < 15) {
            stage_issue(pAh, pAl, pBh, pBl, smb + (uint32_t)((ch & 1) ? 0 : 24576),
                        d0, (ch + 1) * 32);
            asm volatile("cp.async.commit_group;");
            asm volatile("cp.async.wait_group 1;");
        } else {
            asm volatile("cp.async.wait_group 0;");
        }
        __syncthreads();
        #pragma unroll
        for (int ks = 0; ks < 2; ks++) {
            int cidx = ks * 2 + lsel;
            uint32_t ah[2][4], al[2][4], bh[2][4], bl[2][4];
            #pragma unroll
            for (int fi = 0; fi < 2; fi++) {
                uint32_t ad = stb + (uint32_t)((arow + fi * 16) * 64 + ((cidx ^ asw) << 4));
                ldm4(ah[fi], ad);
                ldm4(al[fi], ad + 4096u);
            }
            #pragma unroll
            for (int g = 0; g < 2; g++) {
                uint32_t bd = stb + 8192u + (uint32_t)((brow + g * 16) * 64 + ((cidx ^ bsw) << 4));
                ldm4(bh[g], bd);
                ldm4(bl[g], bd + 8192u);
            }
            // pass 1: ah x bh
            #pragma unroll
            for (int fi = 0; fi < 2; fi++)
                #pragma unroll
                for (int g = 0; g < 2; g++) {
                    mma16816(acc[fi][2*g],   ah[fi], bh[g][0], bh[g][2]);
                    mma16816(acc[fi][2*g+1], ah[fi], bh[g][1], bh[g][3]);
                }
            // pass 2: al x bh
            #pragma unroll
            for (int fi = 0; fi < 2; fi++)
                #pragma unroll
                for (int g = 0; g < 2; g++) {
                    mma16816(acc[fi][2*g],   al[fi], bh[g][0], bh[g][2]);
                    mma16816(acc[fi][2*g+1], al[fi], bh[g][1], bh[g][3]);
                }
            // pass 3: ah x bl
            #pragma unroll
            for (int fi = 0; fi < 2; fi++)
                #pragma unroll
                for (int g = 0; g < 2; g++) {
                    mma16816(acc[fi][2*g],   ah[fi], bl[g][0], bl[g][2]);
                    mma16816(acc[fi][2*g+1], ah[fi], bl[g][1], bl[g][3]);
                }
        }
        __syncthreads();
    }

    if (EPI == 0) {
        // E = exp(score): compute once, write E, derive col stats from E
        float e[2][4][4];
        #pragma unroll
        for (int fi = 0; fi < 2; fi++)
            #pragma unroll
            for (int fj = 0; fj < 4; fj++)
                #pragma unroll
                for (int p = 0; p < 4; p++)
                    e[fi][fj][p] = __expf(acc[fi][fj][p]);
        #pragma unroll
        for (int fi = 0; fi < 2; fi++) {
            size_t r = row0 + warp_i + fi * 16 + (lane >> 2);
            #pragma unroll
            for (int fj = 0; fj < 4; fj++) {
                int cw = col0 + warp_j + fj * 8 + (lane & 3) * 2;
                *(float2*)&Cout[r * 512 + cw]       = make_float2(e[fi][fj][0], e[fi][fj][1]);
                *(float2*)&Cout[(r + 8) * 512 + cw] = make_float2(e[fi][fj][2], e[fi][fj][3]);
            }
        }
        // fused column stats on E over this CTA's 64 rows
        float* smax = (float*)sm;          // [128]
        float* ssum = smax + 128;          // [128]
        float lmax[4][2], lsum[4][2];
        #pragma unroll
        for (int fj = 0; fj < 4; fj++)
            #pragma unroll
            for (int p = 0; p < 2; p++) {
                float a0 = e[0][fj][p], a1 = e[0][fj][2 + p];
                float a2 = e[1][fj][p], a3 = e[1][fj][2 + p];
                lmax[fj][p] = fmaxf(fmaxf(a0, a1), fmaxf(a2, a3));
                lsum[fj][p] = a0 + a1 + a2 + a3;
            }
        #pragma unroll
        for (int off = 4; off < 32; off <<= 1)
            #pragma unroll
            for (int fj = 0; fj < 4; fj++)
                #pragma unroll
                for (int p = 0; p < 2; p++) {
                    lmax[fj][p] = fmaxf(lmax[fj][p], __shfl_xor_sync(0xffffffffu, lmax[fj][p], off));
                    lsum[fj][p] += __shfl_xor_sync(0xffffffffu, lsum[fj][p], off);
                }
        #pragma unroll
        for (int kk = 0; kk < 2; kk++) {
            if ((wid & 1) == kk && lane < 4) {
                #pragma unroll
                for (int fj = 0; fj < 4; fj++)
                    #pragma unroll
                    for (int p = 0; p < 2; p++) {
                        int c = warp_j + fj * 8 + lane * 2 + p;
                        if (kk == 0) { smax[c] = lmax[fj][p]; ssum[c] = lsum[fj][p]; }
                        else { smax[c] = fmaxf(smax[c], lmax[fj][p]); ssum[c] += lsum[fj][p]; }
                    }
            }
            __syncthreads();
        }
        if (tid < 128) {
            atomicMaxF(&g_cmax[col0 + tid], smax[tid]);
            atomicAdd(&g_csum[col0 + tid], ssum[tid]);
        }
    } else {
        // transposed write via smem tile 64 x 128 fp32, stride 129 (conflict-free)
        float* tile = (float*)sm;
        size_t b = row0 >> 12;
        int hw0 = (int)(row0 & 4095);
        float* obase = Cout + b * (1024LL * 4096LL) + (size_t)(512 + col0) * 4096;
        #pragma unroll
        for (int fi = 0; fi < 2; fi++) {
            int rr = warp_i + fi * 16 + (lane >> 2);
            #pragma unroll
            for (int fj = 0; fj < 4; fj++) {
                int cw = warp_j + fj * 8 + (lane & 3) * 2;
                tile[rr * 129 + cw]           = acc[fi][fj][0];
                tile[rr * 129 + cw + 1]       = acc[fi][fj][1];
                tile[(rr + 8) * 129 + cw]     = acc[fi][fj][2];
                tile[(rr + 8) * 129 + cw + 1] = acc[fi][fj][3];
            }
        }
        __syncthreads();
        #pragma unroll
        for (int it = 0; it < 16; it++) {
            int d = wid * 16 + it;
            float v0 = tile[lane * 129 + d];
            float v1 = tile[(lane + 32) * 129 + d];
            obase[(size_t)d * 4096 + hw0 + lane]      = v0;
            obase[(size_t)d * 4096 + hw0 + 32 + lane] = v1;
        }
    }
}

// ---------------- keys prep: splits of keys and keys^T ----------------
__global__ void k_prepkeys(const float* __restrict__ keys) {
    __shared__ float t[32][33];
    int c0 = blockIdx.x * 32;
    int r0 = blockIdx.y * 32;
    int tx = threadIdx.x, ty = threadIdx.y;
    for (int r = ty; r < 32; r += 8) {
        float v = keys[(size_t)(r0 + r) * 512 + c0 + tx];
        t[r][tx] = v;
        __nv_bfloat16 h, l; bf16split(v, h, l);
        g_Bh[(size_t)(r0 + r) * 512 + c0 + tx] = h;
        g_Bl[(size_t)(r0 + r) * 512 + c0 + tx] = l;
    }
    __syncthreads();
    for (int r = ty; r < 32; r += 8) {
        float v = t[tx][r];
        __nv_bfloat16 h, l; bf16split(v, h, l);
        g_BTh[(size_t)(c0 + r) * 512 + r0 + tx] = h;
        g_BTl[(size_t)(c0 + r) * 512 + r0 + tx] = l;
    }
}

// ---------------- init ----------------
__global__ void k_init() {
    int t = blockIdx.x * blockDim.x + threadIdx.x;
    if (t < MDIM) { g_cmax[t] = 0.0f; g_csum[t] = 0.0f; g_count[t] = 0; }
    if (t == 0) { g_comp = 0.0; g_sep = 0.0; }
}

// ---------------- L2 normalize + transpose to (N,C) + bf16 split + direct UQ output ----------------
__global__ void __launch_bounds__(256) k_normalize(const float* __restrict__ query,
                                                   float* __restrict__ out) {
    __shared__ float s[CDIM * 17];
    __shared__ float psum[256];
    __shared__ float rn[16];
    int p0 = blockIdx.x * 16;
    int b = p0 >> 12;
    int hw0 = p0 & 4095;
    const float* qb = query + (size_t)b * CDIM * HWDIM + hw0;
    int tid = threadIdx.x;
    #pragma unroll
    for (int it = 0; it < 32; it++) {
        int i = it * 256 + tid;
        int c = i >> 4, j = i & 15;
        s[c * 17 + j] = qb[(size_t)c * HWDIM + j];
    }
    __syncthreads();
    {
        int j = tid & 15, g = tid >> 4;
        float acc = 0.0f;
        #pragma unroll
        for (int cc = 0; cc < 32; cc++) {
            float v = s[(g * 32 + cc) * 17 + j];
            acc += v * v;
        }
        psum[tid] = acc;
    }
    __syncthreads();
    if (tid < 16) {
        float tot = 0.0f;
        #pragma unroll
        for (int g = 0; g < 16; g++) tot += psum[g * 16 + tid];
        rn[tid] = 1.0f / fmaxf(sqrtf(tot), 1e-12f);
    }
    __syncthreads();
    #pragma unroll
    for (int it = 0; it < 32; it++) {
        int i = it * 256 + tid;
        int c = i & 511, j = i >> 9;
        float v = s[c * 17 + j] * rn[j];
        size_t idx = (size_t)(p0 + j) * CDIM + c;
        __nv_bfloat16 h, l; bf16split(v, h, l);
        g_Ah[idx] = h;
        g_Al[idx] = l;
    }
    float* ob = out + (size_t)b * (1024LL * 4096LL) + hw0;
    #pragma unroll
    for (int it = 0; it < 32; it++) {
        int i = it * 256 + tid;
        int c = i >> 4, j = i & 15;
        ob[(size_t)c * 4096 + j] = s[c * 17 + j] * rn[j];
    }
}

// ---------------- per-row pass on E: softmaxes, top2, w, losses, counts + sm splits ----------------
__global__ void __launch_bounds__(256) k_row(float* __restrict__ out_sq,
                                             float* __restrict__ out_sm,
                                             const float* __restrict__ keys) {
    __shared__ float cinv[512];
    __shared__ double wcomp[8], wsep[8];
    for (int i = threadIdx.x; i < 512; i += 256)
        cinv[i] = 1.0f / g_csum[i];
    __syncthreads();
    int warp = threadIdx.x >> 5, lane = threadIdx.x & 31;
    size_t n = (size_t)blockIdx.x * 8 + warp;
    const float* erow = g_E + n * 512;
    float ev[16];
    #pragma unroll
    for (int t = 0; t < 16; t++) ev[t] = erow[lane + t * 32];

    // top2 on E (exp is monotone -> same indices as on score)
    float v1 = -FLT_MAX, v2 = -FLT_MAX; int i1 = 0, i2 = 0;
    #pragma unroll
    for (int t = 0; t < 16; t++) {
        int c = lane + t * 32; float v = ev[t];
        if (v > v1) { v2 = v1; i2 = i1; v1 = v; i1 = c; }
        else if (v > v2) { v2 = v; i2 = c; }
    }
    #pragma unroll
    for (int off = 16; off; off >>= 1) {
        float ov1 = __shfl_down_sync(0xffffffffu, v1, off);
        int   oi1 = __shfl_down_sync(0xffffffffu, i1, off);
        float ov2 = __shfl_down_sync(0xffffffffu, v2, off);
        int   oi2 = __shfl_down_sync(0xffffffffu, i2, off);
        if (ov1 > v1) { v2 = v1; i2 = i1; v1 = ov1; i1 = oi1; if (ov2 > v2) { v2 = ov2; i2 = oi2; } }
        else if (ov1 > v2) { v2 = ov1; i2 = oi1; }
    }
    v1 = __shfl_sync(0xffffffffu, v1, 0);
    i1 = __shfl_sync(0xffffffffu, i1, 0);
    i2 = __shfl_sync(0xffffffffu, i2, 0);

    // row sum of E
    float rs = 0.0f;
    #pragma unroll
    for (int t = 0; t < 16; t++) rs += ev[t];
    #pragma unroll
    for (int o = 16; o; o >>= 1) rs += __shfl_xor_sync(0xffffffffu, rs, o);
    float inv_rs = 1.0f / rs;
    float* smrow = out_sm + n * 512;
    float* sqrow = out_sq + n * 512;
    #pragma unroll
    for (int t = 0; t < 16; t++) {
        int c = lane + t * 32;
        float sv = ev[t] * inv_rs;
        smrow[c] = sv;
        sqrow[c] = ev[t] * cinv[c];
        __nv_bfloat16 h, l; bf16split(sv, h, l);
        g_Sh[n * 512 + c] = h;
        g_Sl[n * 512 + c] = l;
    }
    if (lane == 0) {
        g_gi[n] = i1;
        g_w[n] = v1 / g_cmax[i1];      // = s_query[n,i1] / colmax(s_query)[i1]
        atomicAdd(&g_count[i1], 1);
    }

    const __nv_bfloat16* qh = g_Ah + n * 512;
    const __nv_bfloat16* ql = g_Al + n * 512;
    const float* pk = keys + (size_t)i1 * 512;
    const float* nk = keys + (size_t)i2 * 512;
    float comp = 0.0f, dp = 0.0f, dn = 0.0f;
    #pragma unroll
    for (int t = 0; t < 16; t++) {
        int c = lane + t * 32;
        float q = __bfloat162float(qh[c]) + __bfloat162float(ql[c]);
        float p = pk[c], gg = nk[c];
        float d0 = q - p; comp += d0 * d0;
        float d1 = d0 + 1e-6f; dp += d1 * d1;
        float d2 = (q - gg) + 1e-6f; dn += d2 * d2;
    }
    #pragma unroll
    for (int o = 16; o; o >>= 1) {
        comp += __shfl_xor_sync(0xffffffffu, comp, o);
        dp   += __shfl_xor_sync(0xffffffffu, dp, o);
        dn   += __shfl_xor_sync(0xffffffffu, dn, o);
    }
    if (lane == 0) {
        wcomp[warp] = (double)comp;
        wsep[warp] = (double)fmaxf(0.0f, sqrtf(dp) - sqrtf(dn) + 1.0f);
    }
    __syncthreads();
    if (threadIdx.x == 0) {
        double c = 0.0, s = 0.0;
        for (int wv = 0; wv < 8; wv++) { c += wcomp[wv]; s += wsep[wv]; }
        atomicAdd(&g_comp, c);
        atomicAdd(&g_sep, s);
    }
}

// ---------------- counting sort of rows by gi ----------------
__global__ void __launch_bounds__(512) k_scan() {
    __shared__ int s[512];
    int t = threadIdx.x;
    int v = g_count[t];
    s[t] = v;
    __syncthreads();
    for (int off = 1; off < 512; off <<= 1) {
        int add = (t >= off) ? s[t - off] : 0;
        __syncthreads();
        s[t] += add;
        __syncthreads();
    }
    g_offset[t + 1] = s[t];
    if (t == 0) g_offset[0] = 0;
    g_cursor[t] = s[t] - v;
}

__global__ void k_scatter() {
    for (int n = blockIdx.x * blockDim.x + threadIdx.x; n < NTOT; n += gridDim.x * blockDim.x) {
        int m = g_gi[n];
        int idx = atomicAdd(&g_cursor[m], 1);
        g_list[idx] = n;
    }
}

// ---------------- memory update: segment sum + l2norm ----------------
__global__ void __launch_bounds__(512) k_update(const float* __restrict__ keys,
                                                float* __restrict__ outUM) {
    int m = blockIdx.x;
    int t = threadIdx.x;
    __shared__ int sln[256];
    __shared__ float slw[256];
    __shared__ float red[16];
    __shared__ float rn_s;
    int beg = g_offset[m], end = g_offset[m + 1];
    float acc = 0.0f;
    for (int base = beg; base < end; base += 256) {
        int cnt = min(256, end - base);
        __syncthreads();
        if (t < cnt) { int n = g_list[base + t]; sln[t] = n; slw[t] = g_w[n]; }
        __syncthreads();
        for (int i = 0; i < cnt; i++) {
            size_t idx = (size_t)sln[i] * 512 + t;
            float q = __bfloat162float(g_Ah[idx]) + __bfloat162float(g_Al[idx]);
            acc += slw[i] * q;
        }
    }
    float um = acc + keys[(size_t)m * 512 + t];
    float ss = um * um;
    #pragma unroll
    for (int o = 16; o; o >>= 1) ss += __shfl_xor_sync(0xffffffffu, ss, o);
    if ((t & 31) == 0) red[t >> 5] = ss;
    __syncthreads();
    if (t == 0) {
        float x = 0.0f;
        for (int i = 0; i < 16; i++) x += red[i];
        rn_s = 1.0f / fmaxf(sqrtf(x), 1e-12f);
    }
    __syncthreads();
    outUM[(size_t)m * 512 + t] = um * rn_s;
}

// ---------------- losses ----------------
__global__ void k_finalize(float* __restrict__ out) {
    out[OFF_SEP] = (float)(g_sep / (double)NTOT);
    out[OFF_COMP] = (float)(g_comp / ((double)NTOT * (double)CDIM));
}

// ---------------- launch ----------------
extern "C" void kernel_launch(void* const* d_in, const int* in_sizes, int n_in,
                              void* d_out, int out_size) {
    const float* query = (const float*)d_in[0];
    const float* keys  = (const float*)d_in[1];
    float* out = (float*)d_out;

    float* p_E = nullptr;
    __nv_bfloat16 *p_Ah = nullptr, *p_Al = nullptr, *p_Sh = nullptr, *p_Sl = nullptr;
    __nv_bfloat16 *p_Bh = nullptr, *p_Bl = nullptr, *p_BTh = nullptr, *p_BTl = nullptr;
    cudaGetSymbolAddress((void**)&p_E, g_E);
    cudaGetSymbolAddress((void**)&p_Ah, g_Ah);
    cudaGetSymbolAddress((void**)&p_Al, g_Al);
    cudaGetSymbolAddress((void**)&p_Sh, g_Sh);
    cudaGetSymbolAddress((void**)&p_Sl, g_Sl);
    cudaGetSymbolAddress((void**)&p_Bh, g_Bh);
    cudaGetSymbolAddress((void**)&p_Bl, g_Bl);
    cudaGetSymbolAddress((void**)&p_BTh, g_BTh);
    cudaGetSymbolAddress((void**)&p_BTl, g_BTl);

    cudaFuncSetAttribute(k_mma<0>, cudaFuncAttributeMaxDynamicSharedMemorySize, 49152);
    cudaFuncSetAttribute(k_mma<1>, cudaFuncAttributeMaxDynamicSharedMemorySize, 49152);

    k_init<<<2, 256>>>();
    k_normalize<<<NTOT / 16, 256>>>(query, out);
    k_prepkeys<<<dim3(16, 16), dim3(32, 8)>>>(keys);
    k_mma<0><<<dim3(4, NTOT / 64), 256, 49152>>>(p_Ah, p_Al, p_Bh, p_Bl, p_E);
    k_row<<<NTOT / 8, 256>>>(out + OFF_SQ, out + OFF_SM, keys);
    k_scan<<<1, 512>>>();
    k_scatter<<<64, 256>>>();
    k_update<<<MDIM, 512>>>(keys, out + OFF_UM);
    k_mma<1><<<dim3(4, NTOT / 64), 256, 49152>>>(p_Sh, p_Sl, p_BTh, p_BTl, out);
    k_finalize<<<1, 1>>>(out);
}